// round 8
// baseline (speedup 1.0000x reference)
#include <cuda_runtime.h>

// ---------------- problem constants ----------------
#define O   130          // output spatial extent per axis
#define P   (O*O)        // 16900
#define O3  2197000      // 130^3
#define CH  12
// input x is 128^3

// ---------------- scratch (device globals) ----------------
// channel-pair layout: g_buf2[((pair*O + z)*P + y*O + w)] = {ch 2p, ch 2p+1}
__device__ float2 g_buf2[(size_t)6 * O3];
__device__ float  g_partial[10 * 67];
__device__ float  g_clip[2];

// shift offsets (oz, oy, ow) for the 6 one-hot dilated stencils, padded coords
__constant__ int c_offs[6][3] = {
    {-1, 1, 1},   // s0: z-minus
    { 1, 1,-1},   // s1: w-minus
    { 1,-1, 1},   // s2: y-minus
    { 1, 1, 3},   // s3: w-plus
    { 3, 1, 1},   // s4: z-plus
    { 1, 3, 1}    // s5: y-plus
};
__constant__ int c_pairs[CH][2] = {
    {1,0},{2,0},{2,1},{3,0},{3,2},{4,1},{4,2},{4,3},{5,0},{5,1},{5,3},{5,4}
};

// ---------------- K1: 3 src planes -> pairwise diff^2 -> W-box -> H-box --------
#define STRIP 10
#define SR    14           // STRIP + 4 boxed halo rows
#define NSTRIP 13          // 13*10 = 130
#define RY    18           // padded-y source rows: jy in [y0-3, y0+14]

__global__ __launch_bounds__(256) void k1_kernel(const float* __restrict__ x) {
    __shared__ float s_x[3][RY][134];   // 28.9 KB
    __shared__ float s_r0[SR][O];       // 7.3 KB (channel 2p)
    __shared__ float s_r1[SR][O];       // 7.3 KB (channel 2p+1)

    const int z   = blockIdx.y;
    const int y0  = blockIdx.x * STRIP;
    const int jy0 = y0 - 3;
    const int tid = threadIdx.x;

    // ---- fill 3 padded source planes (jz = z-1, z+1, z+3), one warp per row ----
    {
        const int wid  = tid >> 5;
        const int lane = tid & 31;
        for (int row = wid; row < 3 * RY; row += 8) {
            int p  = row / RY;
            int ry = row - p * RY;
            int jz = z + 2 * p - 1;
            int jy = jy0 + ry;
            bool rowok = (jz >= 0) & (jz <= 131) & (jy >= 0) & (jy <= 131);
            const float* xrow = x + ((size_t)min(max(jz - 2, 0), 127) << 14)
                                  + (min(max(jy - 2, 0), 127) << 7);
            float* srow = &s_x[p][ry][0];
            #pragma unroll
            for (int k = 0; k < 5; k++) {
                int i = lane + 32 * k;
                if (i < 134) {
                    bool ok = rowok & (i >= 1) & (i <= 132);
                    float v = 0.0f;
                    if (ok) v = __ldg(&xrow[min(max(i - 3, 0), 127)]);
                    srow[i] = v;
                }
            }
        }
    }
    __syncthreads();

    #pragma unroll
    for (int pr = 0; pr < 6; pr++) {
        const int c0 = 2 * pr, c1 = 2 * pr + 1;
        const int sa0 = c_pairs[c0][0], sb0 = c_pairs[c0][1];
        const int sa1 = c_pairs[c1][0], sb1 = c_pairs[c1][1];
        const int pa0 = (c_offs[sa0][0] + 1) >> 1, oya0 = c_offs[sa0][1], owa0 = c_offs[sa0][2];
        const int pb0 = (c_offs[sb0][0] + 1) >> 1, oyb0 = c_offs[sb0][1], owb0 = c_offs[sb0][2];
        const int pa1 = (c_offs[sa1][0] + 1) >> 1, oya1 = c_offs[sa1][1], owa1 = c_offs[sa1][2];
        const int pb1 = (c_offs[sb1][0] + 1) >> 1, oyb1 = c_offs[sb1][1], owb1 = c_offs[sb1][2];

        // ---- W-box of diff^2 for both channels, two outputs per item ----
        for (int idx = tid; idx < SR * 65; idx += 256) {
            int r  = idx / 65;
            int wp = idx - r * 65;
            int w0 = wp << 1;
            int ay = min(max(y0 - 2 + r, 0), O - 1);
            const float* A0 = &s_x[pa0][ay + oya0 - jy0][owa0 + 1];
            const float* B0 = &s_x[pb0][ay + oyb0 - jy0][owb0 + 1];
            const float* A1 = &s_x[pa1][ay + oya1 - jy0][owa1 + 1];
            const float* B1 = &s_x[pb1][ay + oyb1 - jy0][owb1 + 1];
            float t0[6], t1[6];
            #pragma unroll
            for (int k = 0; k < 6; k++) {
                int ww = min(max(w0 - 2 + k, 0), O - 1);
                float d0 = A0[ww] - B0[ww];
                float d1 = A1[ww] - B1[ww];
                t0[k] = d0 * d0;
                t1[k] = d1 * d1;
            }
            s_r0[r][w0]     = t0[0] + t0[1] + t0[2] + t0[3] + t0[4];
            s_r0[r][w0 + 1] = t0[1] + t0[2] + t0[3] + t0[4] + t0[5];
            s_r1[r][w0]     = t1[0] + t1[1] + t1[2] + t1[3] + t1[4];
            s_r1[r][w0 + 1] = t1[1] + t1[2] + t1[3] + t1[4] + t1[5];
        }
        __syncthreads();

        // ---- H-box for both channels, write float2 ----
        float2* gb = &g_buf2[((size_t)pr * O + z) * P + (size_t)y0 * O];
        for (int idx = tid; idx < STRIP * O; idx += 256) {
            int r = idx / O;
            int w = idx - r * O;
            float u0 = s_r0[r][w] + s_r0[r+1][w] + s_r0[r+2][w]
                     + s_r0[r+3][w] + s_r0[r+4][w];
            float u1 = s_r1[r][w] + s_r1[r+1][w] + s_r1[r+2][w]
                     + s_r1[r+3][w] + s_r1[r+4][w];
            gb[idx] = make_float2(u0, u1);
        }
        __syncthreads();
    }
}

// ---------------- K2a: z-box sweep, var partial sums only ----------------
#define ZCH  10
#define ZLEN 13
#define PBLK 67   // ceil(16900/256)

__device__ __forceinline__ void load12(int pz, int v, float t[CH]) {
    #pragma unroll
    for (int pr = 0; pr < 6; pr++) {
        float2 u = g_buf2[((size_t)pr * O + pz) * P + v];
        t[2*pr] = u.x; t[2*pr+1] = u.y;
    }
}

__global__ __launch_bounds__(256) void k2a_kernel() {
    const int tid = threadIdx.x;
    const int v   = blockIdx.x * 256 + tid;
    const int z0  = blockIdx.y * ZLEN;
    const int z1  = min(z0 + ZLEN, O);
    float acc = 0.0f;

    if (v < P) {
        float sums[CH];
        #pragma unroll
        for (int c = 0; c < CH; c++) sums[c] = 0.0f;
        #pragma unroll
        for (int k = 0; k < 5; k++) {
            int pz = min(max(z0 + k - 2, 0), O - 1);
            float t[CH];
            load12(pz, v, t);
            #pragma unroll
            for (int c = 0; c < CH; c++) sums[c] += t[c];
        }

        for (int z = z0; z < z1; z++) {
            float mn = sums[0], tot = sums[0];
            #pragma unroll
            for (int c = 1; c < CH; c++) { mn = fminf(mn, sums[c]); tot += sums[c]; }
            acc += tot * (1.0f / 12.0f) - mn;

            if (z + 1 < z1) {
                int pin  = min(z + 3, O - 1);
                int pout = max(z - 2, 0);
                float ti[CH], to[CH];
                load12(pin, v, ti);
                load12(pout, v, to);
                #pragma unroll
                for (int c = 0; c < CH; c++) sums[c] += ti[c] - to[c];
            }
        }
    }

    __shared__ float red[256];
    red[tid] = acc;
    __syncthreads();
    for (int s = 128; s > 0; s >>= 1) {
        if (tid < s) red[tid] += red[tid + s];
        __syncthreads();
    }
    if (tid == 0) g_partial[blockIdx.y * PBLK + blockIdx.x] = red[0];
}

// ---------------- K2b: deterministic final reduction -> clip bounds ------------
__global__ void k2b_kernel() {
    __shared__ float red[256];
    const int tid = threadIdx.x;
    float a = 0.0f;
    for (int i = tid; i < ZCH * PBLK; i += 256) a += g_partial[i];
    red[tid] = a;
    __syncthreads();
    for (int s = 128; s > 0; s >>= 1) {
        if (tid < s) red[tid] += red[tid + s];
        __syncthreads();
    }
    if (tid == 0) {
        float mean = red[0] / (float)O3;
        g_clip[0] = mean * 0.001f;
        g_clip[1] = mean * 1000.0f;
    }
}

// ---------------- K2c: z-box sweep, write exp(-mind/var) directly --------------
__global__ __launch_bounds__(256) void k2c_kernel(float* __restrict__ out) {
    const int tid = threadIdx.x;
    const int v   = blockIdx.x * 256 + tid;
    const int z0  = blockIdx.y * ZLEN;
    const int z1  = min(z0 + ZLEN, O);

    if (v >= P) return;

    const float lo = g_clip[0], hi = g_clip[1];

    float sums[CH];
    #pragma unroll
    for (int c = 0; c < CH; c++) sums[c] = 0.0f;
    #pragma unroll
    for (int k = 0; k < 5; k++) {
        int pz = min(max(z0 + k - 2, 0), O - 1);
        float t[CH];
        load12(pz, v, t);
        #pragma unroll
        for (int c = 0; c < CH; c++) sums[c] += t[c];
    }

    for (int z = z0; z < z1; z++) {
        float mn = sums[0], tot = sums[0];
        #pragma unroll
        for (int c = 1; c < CH; c++) { mn = fminf(mn, sums[c]); tot += sums[c]; }
        float vc  = fminf(fmaxf(tot * (1.0f / 12.0f) - mn, lo), hi);
        float inv = 1.0f / vc;
        #pragma unroll
        for (int c = 0; c < CH; c++)
            out[(size_t)c * O3 + (size_t)z * P + v] = __expf((mn - sums[c]) * inv);

        if (z + 1 < z1) {
            int pin  = min(z + 3, O - 1);
            int pout = max(z - 2, 0);
            float ti[CH], to[CH];
            load12(pin, v, ti);
            load12(pout, v, to);
            #pragma unroll
            for (int c = 0; c < CH; c++) sums[c] += ti[c] - to[c];
        }
    }
}

// ---------------- launch ----------------
extern "C" void kernel_launch(void* const* d_in, const int* in_sizes, int n_in,
                              void* d_out, int out_size) {
    const float* x = (const float*)d_in[0];
    float* out = (float*)d_out;

    dim3 g1(NSTRIP, O);
    k1_kernel<<<g1, 256>>>(x);

    dim3 g2(PBLK, ZCH);
    k2a_kernel<<<g2, 256>>>();

    k2b_kernel<<<1, 256>>>();

    k2c_kernel<<<g2, 256>>>(out);
}

// round 9
// speedup vs baseline: 1.3334x; 1.3334x over previous
#include <cuda_runtime.h>

// ---------------- problem constants ----------------
#define O   130          // output spatial extent per axis
#define P   (O*O)        // 16900
#define O3  2197000      // 130^3
#define CH  12
// input x is 128^3

// ---------------- scratch (device globals) ----------------
// channel-pair layout: g_buf2[((pair*O + z)*P + y*O + w)] = {ch 2p, ch 2p+1}
__device__ float2 g_buf2[(size_t)6 * O3];
__device__ float  g_partial[10 * 67];
__device__ float  g_clip[2];

// shift offsets (oz, oy, ow) for the 6 one-hot dilated stencils, padded coords
__constant__ int c_offs[6][3] = {
    {-1, 1, 1},   // s0: z-minus
    { 1, 1,-1},   // s1: w-minus
    { 1,-1, 1},   // s2: y-minus
    { 1, 1, 3},   // s3: w-plus
    { 3, 1, 1},   // s4: z-plus
    { 1, 3, 1}    // s5: y-plus
};
__constant__ int c_pairs[CH][2] = {
    {1,0},{2,0},{2,1},{3,0},{3,2},{4,1},{4,2},{4,3},{5,0},{5,1},{5,3},{5,4}
};

// ---------------- K1: 3 src planes -> pairwise diff^2 -> W-box -> H-box --------
#define STRIP 10
#define SR    14           // STRIP + 4 boxed halo rows
#define NSTRIP 13          // 13*10 = 130
#define RY    18           // padded-y source rows: jy in [y0-3, y0+14]

__global__ __launch_bounds__(256) void k1_kernel(const float* __restrict__ x) {
    __shared__ float s_x[3][RY][134];   // 28.9 KB
    __shared__ float s_r0[SR][O];       // 7.3 KB (channel 2p)
    __shared__ float s_r1[SR][O];       // 7.3 KB (channel 2p+1)

    const int z   = blockIdx.y;
    const int y0  = blockIdx.x * STRIP;
    const int jy0 = y0 - 3;
    const int tid = threadIdx.x;

    // ---- fill 3 padded source planes (jz = z-1, z+1, z+3), one warp per row ----
    {
        const int wid  = tid >> 5;
        const int lane = tid & 31;
        for (int row = wid; row < 3 * RY; row += 8) {
            int p  = row / RY;
            int ry = row - p * RY;
            int jz = z + 2 * p - 1;
            int jy = jy0 + ry;
            bool rowok = (jz >= 0) & (jz <= 131) & (jy >= 0) & (jy <= 131);
            const float* xrow = x + ((size_t)min(max(jz - 2, 0), 127) << 14)
                                  + (min(max(jy - 2, 0), 127) << 7);
            float* srow = &s_x[p][ry][0];
            #pragma unroll
            for (int k = 0; k < 5; k++) {
                int i = lane + 32 * k;
                if (i < 134) {
                    bool ok = rowok & (i >= 1) & (i <= 132);
                    float v = 0.0f;
                    if (ok) v = __ldg(&xrow[min(max(i - 3, 0), 127)]);
                    srow[i] = v;
                }
            }
        }
    }
    __syncthreads();

    #pragma unroll
    for (int pr = 0; pr < 6; pr++) {
        const int c0 = 2 * pr, c1 = 2 * pr + 1;
        const int sa0 = c_pairs[c0][0], sb0 = c_pairs[c0][1];
        const int sa1 = c_pairs[c1][0], sb1 = c_pairs[c1][1];
        const int pa0 = (c_offs[sa0][0] + 1) >> 1, oya0 = c_offs[sa0][1], owa0 = c_offs[sa0][2];
        const int pb0 = (c_offs[sb0][0] + 1) >> 1, oyb0 = c_offs[sb0][1], owb0 = c_offs[sb0][2];
        const int pa1 = (c_offs[sa1][0] + 1) >> 1, oya1 = c_offs[sa1][1], owa1 = c_offs[sa1][2];
        const int pb1 = (c_offs[sb1][0] + 1) >> 1, oyb1 = c_offs[sb1][1], owb1 = c_offs[sb1][2];

        // ---- W-box of diff^2: each thread = one row-segment of 10 outputs ----
        // taps j = w0-2 .. w0+11 (14), running 5-tap sum, 2 channels
        for (int idx = tid; idx < SR * NSTRIP; idx += 256) {
            int r  = idx / NSTRIP;
            int sg = idx - r * NSTRIP;
            int w0 = sg * 10;
            int ay = min(max(y0 - 2 + r, 0), O - 1);
            const float* A0 = &s_x[pa0][ay + oya0 - jy0][owa0 + 1];
            const float* B0 = &s_x[pb0][ay + oyb0 - jy0][owb0 + 1];
            const float* A1 = &s_x[pa1][ay + oya1 - jy0][owa1 + 1];
            const float* B1 = &s_x[pb1][ay + oyb1 - jy0][owb1 + 1];
            float d20[14], d21[14];
            #pragma unroll
            for (int k = 0; k < 14; k++) {
                int ww = min(max(w0 - 2 + k, 0), O - 1);
                float a = A0[ww] - B0[ww];
                float b = A1[ww] - B1[ww];
                d20[k] = a * a;
                d21[k] = b * b;
            }
            float s0 = d20[0] + d20[1] + d20[2] + d20[3] + d20[4];
            float s1 = d21[0] + d21[1] + d21[2] + d21[3] + d21[4];
            float* r0 = &s_r0[r][w0];
            float* r1 = &s_r1[r][w0];
            #pragma unroll
            for (int j = 0; j < 10; j++) {
                r0[j] = s0;
                r1[j] = s1;
                if (j < 9) {
                    s0 += d20[j + 5] - d20[j];
                    s1 += d21[j + 5] - d21[j];
                }
            }
        }
        __syncthreads();

        // ---- H-box: each thread = one column half (5 outputs), 2 channels ----
        float2* gb = &g_buf2[((size_t)pr * O + z) * P + (size_t)y0 * O];
        for (int idx = tid; idx < 2 * O; idx += 256) {
            int w   = idx % O;
            int ry0 = (idx / O) * 5;
            float t0[9], t1[9];
            #pragma unroll
            for (int k = 0; k < 9; k++) {
                t0[k] = s_r0[ry0 + k][w];
                t1[k] = s_r1[ry0 + k][w];
            }
            float s0 = t0[0] + t0[1] + t0[2] + t0[3] + t0[4];
            float s1 = t1[0] + t1[1] + t1[2] + t1[3] + t1[4];
            #pragma unroll
            for (int j = 0; j < 5; j++) {
                gb[(ry0 + j) * O + w] = make_float2(s0, s1);
                if (j < 4) {
                    s0 += t0[j + 5] - t0[j];
                    s1 += t1[j + 5] - t1[j];
                }
            }
        }
        __syncthreads();
    }
}

// ---------------- K2: z-box sweep, ring window, write mind + var partials ------
#define ZCH  10
#define ZLEN 13
#define PBLK 67   // ceil(16900/256)

__global__ __launch_bounds__(256) void k2_kernel(float* __restrict__ mind) {
    const int tid = threadIdx.x;
    const int v   = blockIdx.x * 256 + tid;
    const int z0  = blockIdx.y * ZLEN;
    const int z1  = min(z0 + ZLEN, O);
    float acc = 0.0f;

    if (v < P) {
        float sums[CH], w0[CH], w1[CH], w2[CH], w3[CH];
        #pragma unroll
        for (int c = 0; c < CH; c++) sums[c] = 0.0f;

        #pragma unroll
        for (int q = 0; q < 4; q++) {
            int pz = min(max(z0 - 2 + q, 0), O - 1);
            float t[CH];
            #pragma unroll
            for (int pr = 0; pr < 6; pr++) {
                float2 u = g_buf2[((size_t)pr * O + pz) * P + v];
                t[2*pr] = u.x; t[2*pr+1] = u.y;
            }
            #pragma unroll
            for (int c = 0; c < CH; c++) {
                sums[c] += t[c];
                if (q == 0) w0[c] = t[c];
                else if (q == 1) w1[c] = t[c];
                else if (q == 2) w2[c] = t[c];
                else w3[c] = t[c];
            }
        }

        for (int z = z0; z < z1; z++) {
            int pz = min(z + 2, O - 1);
            float nv[CH];
            #pragma unroll
            for (int pr = 0; pr < 6; pr++) {
                float2 u = g_buf2[((size_t)pr * O + pz) * P + v];
                nv[2*pr] = u.x; nv[2*pr+1] = u.y;
            }
            #pragma unroll
            for (int c = 0; c < CH; c++) sums[c] += nv[c];

            float mn = sums[0], tot = sums[0];
            #pragma unroll
            for (int c = 1; c < CH; c++) { mn = fminf(mn, sums[c]); tot += sums[c]; }

            #pragma unroll
            for (int c = 0; c < CH; c++)
                mind[(size_t)c * O3 + (size_t)z * P + v] = (sums[c] - mn) * (1.0f / 125.0f);

            acc += (tot * (1.0f / 12.0f) - mn) * (1.0f / 125.0f);

            #pragma unroll
            for (int c = 0; c < CH; c++) {
                sums[c] -= w0[c];
                w0[c] = w1[c]; w1[c] = w2[c]; w2[c] = w3[c]; w3[c] = nv[c];
            }
        }
    }

    __shared__ float red[256];
    red[tid] = acc;
    __syncthreads();
    for (int s = 128; s > 0; s >>= 1) {
        if (tid < s) red[tid] += red[tid + s];
        __syncthreads();
    }
    if (tid == 0) g_partial[blockIdx.y * PBLK + blockIdx.x] = red[0];
}

// ---------------- K2b: deterministic final reduction -> clip bounds ------------
__global__ void k2b_kernel() {
    __shared__ float red[256];
    const int tid = threadIdx.x;
    float a = 0.0f;
    for (int i = tid; i < ZCH * PBLK; i += 256) a += g_partial[i];
    red[tid] = a;
    __syncthreads();
    for (int s = 128; s > 0; s >>= 1) {
        if (tid < s) red[tid] += red[tid + s];
        __syncthreads();
    }
    if (tid == 0) {
        float mean = red[0] / (float)O3;
        g_clip[0] = mean * 0.001f;
        g_clip[1] = mean * 1000.0f;
    }
}

// ---------------- K3: recompute var from channels, exp, float4 ----------------
#define Q4 (O3 / 4)    // 549250

__global__ __launch_bounds__(256) void k3_kernel(float* __restrict__ out) {
    const int v4 = blockIdx.x * 256 + threadIdx.x;
    if (v4 >= Q4) return;
    float4* o4 = (float4*)out;

    float4 m[CH];
    #pragma unroll
    for (int c = 0; c < CH; c++) m[c] = o4[(size_t)c * Q4 + v4];

    float sx = 0.f, sy = 0.f, sz = 0.f, sw = 0.f;
    #pragma unroll
    for (int c = 0; c < CH; c++) {
        sx += m[c].x; sy += m[c].y; sz += m[c].z; sw += m[c].w;
    }
    const float lo = g_clip[0], hi = g_clip[1];
    float ix = 1.0f / fminf(fmaxf(sx * (1.0f/12.0f), lo), hi);
    float iy = 1.0f / fminf(fmaxf(sy * (1.0f/12.0f), lo), hi);
    float iz = 1.0f / fminf(fmaxf(sz * (1.0f/12.0f), lo), hi);
    float iw = 1.0f / fminf(fmaxf(sw * (1.0f/12.0f), lo), hi);

    #pragma unroll
    for (int c = 0; c < CH; c++) {
        float4 r;
        r.x = __expf(-m[c].x * ix);
        r.y = __expf(-m[c].y * iy);
        r.z = __expf(-m[c].z * iz);
        r.w = __expf(-m[c].w * iw);
        o4[(size_t)c * Q4 + v4] = r;
    }
}

// ---------------- launch ----------------
extern "C" void kernel_launch(void* const* d_in, const int* in_sizes, int n_in,
                              void* d_out, int out_size) {
    const float* x = (const float*)d_in[0];
    float* out = (float*)d_out;

    dim3 g1(NSTRIP, O);
    k1_kernel<<<g1, 256>>>(x);

    dim3 g2(PBLK, ZCH);
    k2_kernel<<<g2, 256>>>(out);

    k2b_kernel<<<1, 256>>>();

    k3_kernel<<<(Q4 + 255) / 256, 256>>>(out);
}

// round 10
// speedup vs baseline: 1.3471x; 1.0103x over previous
#include <cuda_runtime.h>

// ---------------- problem constants ----------------
#define O   130          // output spatial extent per axis
#define P   (O*O)        // 16900
#define O3  2197000      // 130^3
#define CH  12
// input x is 128^3

// ---------------- scratch (device globals) ----------------
// channel-quad layout: g_buf4[((q*O + z)*P + y*O + w)] = {ch 4q .. 4q+3}
__device__ float4 g_buf4[(size_t)3 * O3];
__device__ float  g_partial[10 * 67];
__device__ float  g_clip[2];

// shift offsets (oz, oy, ow) for the 6 one-hot dilated stencils, padded coords
__constant__ int c_offs[6][3] = {
    {-1, 1, 1},   // s0: z-minus
    { 1, 1,-1},   // s1: w-minus
    { 1,-1, 1},   // s2: y-minus
    { 1, 1, 3},   // s3: w-plus
    { 3, 1, 1},   // s4: z-plus
    { 1, 3, 1}    // s5: y-plus
};
__constant__ int c_pairs[CH][2] = {
    {1,0},{2,0},{2,1},{3,0},{3,2},{4,1},{4,2},{4,3},{5,0},{5,1},{5,3},{5,4}
};

// ---------------- K1: 3 src planes -> pairwise diff^2 -> W-box -> H-box --------
#define STRIP 10
#define SR    14           // STRIP + 4 boxed halo rows
#define NSTRIP 13          // 13*10 = 130
#define RY    18           // padded-y source rows: jy in [y0-3, y0+14]
#define SXN   (3*RY*134)   // 7236 floats
#define SRN   (SR*O)       // 1820 floats per row buffer
#define K1_SMEM ((SXN + 4*SRN) * 4)   // 58.1 KB

__global__ __launch_bounds__(256) void k1_kernel(const float* __restrict__ x) {
    extern __shared__ float sm[];
    float* s_x = sm;                       // [3][RY][134]
    float* s_r[4] = { sm + SXN, sm + SXN + SRN,
                      sm + SXN + 2*SRN, sm + SXN + 3*SRN };  // [SR][O] each

    const int z   = blockIdx.y;
    const int y0  = blockIdx.x * STRIP;
    const int jy0 = y0 - 3;
    const int tid = threadIdx.x;

    // ---- fill 3 padded source planes (jz = z-1, z+1, z+3), one warp per row ----
    {
        const int wid  = tid >> 5;
        const int lane = tid & 31;
        for (int row = wid; row < 3 * RY; row += 8) {
            int p  = row / RY;
            int ry = row - p * RY;
            int jz = z + 2 * p - 1;
            int jy = jy0 + ry;
            bool rowok = (jz >= 0) & (jz <= 131) & (jy >= 0) & (jy <= 131);
            const float* xrow = x + ((size_t)min(max(jz - 2, 0), 127) << 14)
                                  + (min(max(jy - 2, 0), 127) << 7);
            float* srow = &s_x[(p * RY + ry) * 134];
            #pragma unroll
            for (int k = 0; k < 5; k++) {
                int i = lane + 32 * k;
                if (i < 134) {
                    bool ok = rowok & (i >= 1) & (i <= 132);
                    float v = 0.0f;
                    if (ok) v = __ldg(&xrow[min(max(i - 3, 0), 127)]);
                    srow[i] = v;
                }
            }
        }
    }
    __syncthreads();

    #pragma unroll
    for (int qd = 0; qd < 3; qd++) {
        // ---- W-box for the two pairs of this quad (4 channels) ----
        #pragma unroll
        for (int half = 0; half < 2; half++) {
            const int pr = qd * 2 + half;
            const int c0 = 2 * pr, c1 = 2 * pr + 1;
            const int sa0 = c_pairs[c0][0], sb0 = c_pairs[c0][1];
            const int sa1 = c_pairs[c1][0], sb1 = c_pairs[c1][1];
            const int pa0 = (c_offs[sa0][0] + 1) >> 1, oya0 = c_offs[sa0][1], owa0 = c_offs[sa0][2];
            const int pb0 = (c_offs[sb0][0] + 1) >> 1, oyb0 = c_offs[sb0][1], owb0 = c_offs[sb0][2];
            const int pa1 = (c_offs[sa1][0] + 1) >> 1, oya1 = c_offs[sa1][1], owa1 = c_offs[sa1][2];
            const int pb1 = (c_offs[sb1][0] + 1) >> 1, oyb1 = c_offs[sb1][1], owb1 = c_offs[sb1][2];
            float* r0 = s_r[2 * half];
            float* r1 = s_r[2 * half + 1];

            for (int idx = tid; idx < SR * NSTRIP; idx += 256) {
                int r  = idx / NSTRIP;
                int sg = idx - r * NSTRIP;
                int w0 = sg * 10;
                int ay = min(max(y0 - 2 + r, 0), O - 1);
                const float* A0 = &s_x[(pa0 * RY + ay + oya0 - jy0) * 134 + owa0 + 1];
                const float* B0 = &s_x[(pb0 * RY + ay + oyb0 - jy0) * 134 + owb0 + 1];
                const float* A1 = &s_x[(pa1 * RY + ay + oya1 - jy0) * 134 + owa1 + 1];
                const float* B1 = &s_x[(pb1 * RY + ay + oyb1 - jy0) * 134 + owb1 + 1];
                float d20[14], d21[14];
                #pragma unroll
                for (int k = 0; k < 14; k++) {
                    int ww = min(max(w0 - 2 + k, 0), O - 1);
                    float a = A0[ww] - B0[ww];
                    float b = A1[ww] - B1[ww];
                    d20[k] = a * a;
                    d21[k] = b * b;
                }
                float s0 = d20[0] + d20[1] + d20[2] + d20[3] + d20[4];
                float s1 = d21[0] + d21[1] + d21[2] + d21[3] + d21[4];
                float* p0 = &r0[r * O + w0];
                float* p1 = &r1[r * O + w0];
                #pragma unroll
                for (int j = 0; j < 10; j++) {
                    p0[j] = s0;
                    p1[j] = s1;
                    if (j < 9) {
                        s0 += d20[j + 5] - d20[j];
                        s1 += d21[j + 5] - d21[j];
                    }
                }
            }
        }
        __syncthreads();

        // ---- H-box for 4 channels, write float4 ----
        float4* gb = &g_buf4[((size_t)qd * O + z) * P + (size_t)y0 * O];
        for (int idx = tid; idx < 2 * O; idx += 256) {
            int w   = idx % O;
            int ry0 = (idx / O) * 5;
            float t0[9], t1[9], t2[9], t3[9];
            #pragma unroll
            for (int k = 0; k < 9; k++) {
                t0[k] = s_r[0][(ry0 + k) * O + w];
                t1[k] = s_r[1][(ry0 + k) * O + w];
                t2[k] = s_r[2][(ry0 + k) * O + w];
                t3[k] = s_r[3][(ry0 + k) * O + w];
            }
            float s0 = t0[0] + t0[1] + t0[2] + t0[3] + t0[4];
            float s1 = t1[0] + t1[1] + t1[2] + t1[3] + t1[4];
            float s2 = t2[0] + t2[1] + t2[2] + t2[3] + t2[4];
            float s3 = t3[0] + t3[1] + t3[2] + t3[3] + t3[4];
            #pragma unroll
            for (int j = 0; j < 5; j++) {
                gb[(ry0 + j) * O + w] = make_float4(s0, s1, s2, s3);
                if (j < 4) {
                    s0 += t0[j + 5] - t0[j];
                    s1 += t1[j + 5] - t1[j];
                    s2 += t2[j + 5] - t2[j];
                    s3 += t3[j + 5] - t3[j];
                }
            }
        }
        __syncthreads();
    }
}

// ---------------- K2: z-box sweep, ring window, write mind + var partials ------
#define ZCH  10
#define ZLEN 13
#define PBLK 67   // ceil(16900/256)

__global__ __launch_bounds__(256) void k2_kernel(float* __restrict__ mind) {
    const int tid = threadIdx.x;
    const int v   = blockIdx.x * 256 + tid;
    const int z0  = blockIdx.y * ZLEN;
    const int z1  = min(z0 + ZLEN, O);
    float acc = 0.0f;

    if (v < P) {
        float sums[CH], w0[CH], w1[CH], w2[CH], w3[CH];
        #pragma unroll
        for (int c = 0; c < CH; c++) sums[c] = 0.0f;

        #pragma unroll
        for (int q = 0; q < 4; q++) {
            int pz = min(max(z0 - 2 + q, 0), O - 1);
            float t[CH];
            #pragma unroll
            for (int qd = 0; qd < 3; qd++) {
                float4 u = g_buf4[((size_t)qd * O + pz) * P + v];
                t[4*qd] = u.x; t[4*qd+1] = u.y; t[4*qd+2] = u.z; t[4*qd+3] = u.w;
            }
            #pragma unroll
            for (int c = 0; c < CH; c++) {
                sums[c] += t[c];
                if (q == 0) w0[c] = t[c];
                else if (q == 1) w1[c] = t[c];
                else if (q == 2) w2[c] = t[c];
                else w3[c] = t[c];
            }
        }

        for (int z = z0; z < z1; z++) {
            int pz = min(z + 2, O - 1);
            float nv[CH];
            #pragma unroll
            for (int qd = 0; qd < 3; qd++) {
                float4 u = g_buf4[((size_t)qd * O + pz) * P + v];
                nv[4*qd] = u.x; nv[4*qd+1] = u.y; nv[4*qd+2] = u.z; nv[4*qd+3] = u.w;
            }
            #pragma unroll
            for (int c = 0; c < CH; c++) sums[c] += nv[c];

            float mn = sums[0], tot = sums[0];
            #pragma unroll
            for (int c = 1; c < CH; c++) { mn = fminf(mn, sums[c]); tot += sums[c]; }

            #pragma unroll
            for (int c = 0; c < CH; c++)
                mind[(size_t)c * O3 + (size_t)z * P + v] = (sums[c] - mn) * (1.0f / 125.0f);

            acc += (tot * (1.0f / 12.0f) - mn) * (1.0f / 125.0f);

            #pragma unroll
            for (int c = 0; c < CH; c++) {
                sums[c] -= w0[c];
                w0[c] = w1[c]; w1[c] = w2[c]; w2[c] = w3[c]; w3[c] = nv[c];
            }
        }
    }

    __shared__ float red[256];
    red[tid] = acc;
    __syncthreads();
    for (int s = 128; s > 0; s >>= 1) {
        if (tid < s) red[tid] += red[tid + s];
        __syncthreads();
    }
    if (tid == 0) g_partial[blockIdx.y * PBLK + blockIdx.x] = red[0];
}

// ---------------- K2b: deterministic final reduction -> clip bounds ------------
__global__ void k2b_kernel() {
    __shared__ float red[256];
    const int tid = threadIdx.x;
    float a = 0.0f;
    for (int i = tid; i < ZCH * PBLK; i += 256) a += g_partial[i];
    red[tid] = a;
    __syncthreads();
    for (int s = 128; s > 0; s >>= 1) {
        if (tid < s) red[tid] += red[tid + s];
        __syncthreads();
    }
    if (tid == 0) {
        float mean = red[0] / (float)O3;
        g_clip[0] = mean * 0.001f;
        g_clip[1] = mean * 1000.0f;
    }
}

// ---------------- K3: recompute var from channels, exp, float4 ----------------
#define Q4 (O3 / 4)    // 549250

__global__ __launch_bounds__(256) void k3_kernel(float* __restrict__ out) {
    const int v4 = blockIdx.x * 256 + threadIdx.x;
    if (v4 >= Q4) return;
    float4* o4 = (float4*)out;

    float4 m[CH];
    #pragma unroll
    for (int c = 0; c < CH; c++) m[c] = o4[(size_t)c * Q4 + v4];

    float sx = 0.f, sy = 0.f, sz = 0.f, sw = 0.f;
    #pragma unroll
    for (int c = 0; c < CH; c++) {
        sx += m[c].x; sy += m[c].y; sz += m[c].z; sw += m[c].w;
    }
    const float lo = g_clip[0], hi = g_clip[1];
    float ix = 1.0f / fminf(fmaxf(sx * (1.0f/12.0f), lo), hi);
    float iy = 1.0f / fminf(fmaxf(sy * (1.0f/12.0f), lo), hi);
    float iz = 1.0f / fminf(fmaxf(sz * (1.0f/12.0f), lo), hi);
    float iw = 1.0f / fminf(fmaxf(sw * (1.0f/12.0f), lo), hi);

    #pragma unroll
    for (int c = 0; c < CH; c++) {
        float4 r;
        r.x = __expf(-m[c].x * ix);
        r.y = __expf(-m[c].y * iy);
        r.z = __expf(-m[c].z * iz);
        r.w = __expf(-m[c].w * iw);
        o4[(size_t)c * Q4 + v4] = r;
    }
}

// ---------------- launch ----------------
extern "C" void kernel_launch(void* const* d_in, const int* in_sizes, int n_in,
                              void* d_out, int out_size) {
    const float* x = (const float*)d_in[0];
    float* out = (float*)d_out;

    cudaFuncSetAttribute(k1_kernel,
                         cudaFuncAttributeMaxDynamicSharedMemorySize, K1_SMEM);

    dim3 g1(NSTRIP, O);
    k1_kernel<<<g1, 256, K1_SMEM>>>(x);

    dim3 g2(PBLK, ZCH);
    k2_kernel<<<g2, 256>>>(out);

    k2b_kernel<<<1, 256>>>();

    k3_kernel<<<(Q4 + 255) / 256, 256>>>(out);
}

// round 13
// speedup vs baseline: 1.5000x; 1.1135x over previous
#include <cuda_runtime.h>

// ---------------- problem constants ----------------
#define O   130          // output spatial extent per axis
#define P   (O*O)        // 16900
#define O3  2197000      // 130^3
#define CH  12
// input x is 128^3

// ---------------- scratch (device globals) ----------------
// channel-quad layout: g_buf4[((q*O + z)*P + y*O + w)] = 4 permuted channels
__device__ float4 g_buf4[(size_t)3 * O3];
__device__ float  g_partial[10 * 67];
__device__ float  g_clip[2];

// shift offsets (oz, oy, ow) for the 6 one-hot dilated stencils, padded coords
__device__ constexpr int OFFS[6][3] = {
    {-1, 1, 1},   // s0: z-minus
    { 1, 1,-1},   // s1: w-minus
    { 1,-1, 1},   // s2: y-minus
    { 1, 1, 3},   // s3: w-plus
    { 3, 1, 1},   // s4: z-plus
    { 1, 3, 1}    // s5: y-plus
};
// quad partition of the 12 pairs: each quad spans exactly 4 shifts
__device__ constexpr int QS[3][4] = {        // shift ids per quad
    {0, 1, 2, 3},
    {0, 3, 4, 5},
    {1, 2, 4, 5}
};
__device__ constexpr int QP[3][4][2] = {     // channel pairs as local indices into QS[qd]
    { {1,0}, {2,0}, {2,1}, {3,2} },   // (1,0) (2,0) (2,1) (3,2)
    { {1,0}, {2,1}, {3,0}, {3,1} },   // (3,0) (4,3) (5,0) (5,3)
    { {2,0}, {2,1}, {3,0}, {3,2} }    // (4,1) (4,2) (5,1) (5,4)
};
// output channel id of each quad lane
__constant__ int CHMAP[12] = {0,1,2,4,  3,7,8,10,  5,6,9,11};

// ---------------- K1: 3 src planes -> quad diff^2 -> W-box -> H-box ------------
#define STRIP 10
#define SR    14           // STRIP + 4 boxed halo rows
#define NSTRIP 13          // 13*10 = 130
#define RY    18           // padded-y source rows: jy in [y0-3, y0+14]
#define SXN   (3*RY*134)   // 7236 floats
#define SRN   (SR*O)       // 1820 floats per row buffer
#define K1_SMEM ((SXN + 4*SRN) * 4)   // 58.1 KB

__global__ __launch_bounds__(256) void k1_kernel(const float* __restrict__ x) {
    extern __shared__ float sm[];
    float* s_x = sm;                       // [3][RY][134]
    float* s_r[4] = { sm + SXN, sm + SXN + SRN,
                      sm + SXN + 2*SRN, sm + SXN + 3*SRN };  // [SR][O] each

    const int z   = blockIdx.y;
    const int y0  = blockIdx.x * STRIP;
    const int jy0 = y0 - 3;
    const int tid = threadIdx.x;

    // ---- fill 3 padded source planes (jz = z-1, z+1, z+3), one warp per row ----
    {
        const int wid  = tid >> 5;
        const int lane = tid & 31;
        for (int row = wid; row < 3 * RY; row += 8) {
            int p  = row / RY;
            int ry = row - p * RY;
            int jz = z + 2 * p - 1;
            int jy = jy0 + ry;
            bool rowok = (jz >= 0) & (jz <= 131) & (jy >= 0) & (jy <= 131);
            const float* xrow = x + ((size_t)min(max(jz - 2, 0), 127) << 14)
                                  + (min(max(jy - 2, 0), 127) << 7);
            float* srow = &s_x[(p * RY + ry) * 134];
            #pragma unroll
            for (int k = 0; k < 5; k++) {
                int i = lane + 32 * k;
                if (i < 134) {
                    bool ok = rowok & (i >= 1) & (i <= 132);
                    float v = 0.0f;
                    if (ok) v = __ldg(&xrow[min(max(i - 3, 0), 127)]);
                    srow[i] = v;
                }
            }
        }
    }
    __syncthreads();

    #pragma unroll
    for (int qd = 0; qd < 3; qd++) {
        // ---- W-box: 4 shift rows shared across 4 channels ----
        for (int idx = tid; idx < SR * NSTRIP; idx += 256) {
            int r  = idx / NSTRIP;
            int sg = idx - r * NSTRIP;
            int w0 = sg * 10;
            int ay = min(max(y0 - 2 + r, 0), O - 1);

            const float* R[4];
            #pragma unroll
            for (int l = 0; l < 4; l++) {
                const int s  = QS[qd][l];
                const int p  = (OFFS[s][0] + 1) >> 1;
                R[l] = &s_x[(p * RY + ay + OFFS[s][1] - jy0) * 134 + OFFS[s][2] + 1];
            }

            float d2[4][14];
            #pragma unroll
            for (int k = 0; k < 14; k++) {
                int ww = min(max(w0 - 2 + k, 0), O - 1);
                float v[4];
                v[0] = R[0][ww]; v[1] = R[1][ww]; v[2] = R[2][ww]; v[3] = R[3][ww];
                #pragma unroll
                for (int j = 0; j < 4; j++) {
                    float d = v[QP[qd][j][0]] - v[QP[qd][j][1]];
                    d2[j][k] = d * d;
                }
            }

            float s0 = d2[0][0] + d2[0][1] + d2[0][2] + d2[0][3] + d2[0][4];
            float s1 = d2[1][0] + d2[1][1] + d2[1][2] + d2[1][3] + d2[1][4];
            float s2 = d2[2][0] + d2[2][1] + d2[2][2] + d2[2][3] + d2[2][4];
            float s3 = d2[3][0] + d2[3][1] + d2[3][2] + d2[3][3] + d2[3][4];
            float* p0 = &s_r[0][r * O + w0];
            float* p1 = &s_r[1][r * O + w0];
            float* p2 = &s_r[2][r * O + w0];
            float* p3 = &s_r[3][r * O + w0];
            #pragma unroll
            for (int j = 0; j < 10; j++) {
                p0[j] = s0; p1[j] = s1; p2[j] = s2; p3[j] = s3;
                if (j < 9) {
                    s0 += d2[0][j + 5] - d2[0][j];
                    s1 += d2[1][j + 5] - d2[1][j];
                    s2 += d2[2][j + 5] - d2[2][j];
                    s3 += d2[3][j + 5] - d2[3][j];
                }
            }
        }
        __syncthreads();

        // ---- H-box for 4 channels, write float4 ----
        float4* gb = &g_buf4[((size_t)qd * O + z) * P + (size_t)y0 * O];
        for (int idx = tid; idx < 2 * O; idx += 256) {
            int w   = idx % O;
            int ry0 = (idx / O) * 5;
            float t0[9], t1[9], t2[9], t3[9];
            #pragma unroll
            for (int k = 0; k < 9; k++) {
                t0[k] = s_r[0][(ry0 + k) * O + w];
                t1[k] = s_r[1][(ry0 + k) * O + w];
                t2[k] = s_r[2][(ry0 + k) * O + w];
                t3[k] = s_r[3][(ry0 + k) * O + w];
            }
            float s0 = t0[0] + t0[1] + t0[2] + t0[3] + t0[4];
            float s1 = t1[0] + t1[1] + t1[2] + t1[3] + t1[4];
            float s2 = t2[0] + t2[1] + t2[2] + t2[3] + t2[4];
            float s3 = t3[0] + t3[1] + t3[2] + t3[3] + t3[4];
            #pragma unroll
            for (int j = 0; j < 5; j++) {
                gb[(ry0 + j) * O + w] = make_float4(s0, s1, s2, s3);
                if (j < 4) {
                    s0 += t0[j + 5] - t0[j];
                    s1 += t1[j + 5] - t1[j];
                    s2 += t2[j + 5] - t2[j];
                    s3 += t3[j + 5] - t3[j];
                }
            }
        }
        __syncthreads();
    }
}

// ---------------- K2: z-box sweep, ring window, write mind + var partials ------
#define ZCH  10
#define ZLEN 13
#define PBLK 67   // ceil(16900/256)

__global__ __launch_bounds__(256) void k2_kernel(float* __restrict__ mind) {
    const int tid = threadIdx.x;
    const int v   = blockIdx.x * 256 + tid;
    const int z0  = blockIdx.y * ZLEN;
    const int z1  = min(z0 + ZLEN, O);
    float acc = 0.0f;

    if (v < P) {
        float sums[CH], w0[CH], w1[CH], w2[CH], w3[CH];
        #pragma unroll
        for (int c = 0; c < CH; c++) sums[c] = 0.0f;

        #pragma unroll
        for (int q = 0; q < 4; q++) {
            int pz = min(max(z0 - 2 + q, 0), O - 1);
            float t[CH];
            #pragma unroll
            for (int qd = 0; qd < 3; qd++) {
                float4 u = g_buf4[((size_t)qd * O + pz) * P + v];
                t[4*qd] = u.x; t[4*qd+1] = u.y; t[4*qd+2] = u.z; t[4*qd+3] = u.w;
            }
            #pragma unroll
            for (int c = 0; c < CH; c++) {
                sums[c] += t[c];
                if (q == 0) w0[c] = t[c];
                else if (q == 1) w1[c] = t[c];
                else if (q == 2) w2[c] = t[c];
                else w3[c] = t[c];
            }
        }

        for (int z = z0; z < z1; z++) {
            int pz = min(z + 2, O - 1);
            float nv[CH];
            #pragma unroll
            for (int qd = 0; qd < 3; qd++) {
                float4 u = g_buf4[((size_t)qd * O + pz) * P + v];
                nv[4*qd] = u.x; nv[4*qd+1] = u.y; nv[4*qd+2] = u.z; nv[4*qd+3] = u.w;
            }
            #pragma unroll
            for (int c = 0; c < CH; c++) sums[c] += nv[c];

            float mn = sums[0], tot = sums[0];
            #pragma unroll
            for (int c = 1; c < CH; c++) { mn = fminf(mn, sums[c]); tot += sums[c]; }

            // write each permuted lane to its true output channel
            #pragma unroll
            for (int c = 0; c < CH; c++)
                mind[(size_t)CHMAP[c] * O3 + (size_t)z * P + v] =
                    (sums[c] - mn) * (1.0f / 125.0f);

            acc += (tot * (1.0f / 12.0f) - mn) * (1.0f / 125.0f);

            #pragma unroll
            for (int c = 0; c < CH; c++) {
                sums[c] -= w0[c];
                w0[c] = w1[c]; w1[c] = w2[c]; w2[c] = w3[c]; w3[c] = nv[c];
            }
        }
    }

    __shared__ float red[256];
    red[tid] = acc;
    __syncthreads();
    for (int s = 128; s > 0; s >>= 1) {
        if (tid < s) red[tid] += red[tid + s];
        __syncthreads();
    }
    if (tid == 0) g_partial[blockIdx.y * PBLK + blockIdx.x] = red[0];
}

// ---------------- K2b: deterministic final reduction -> clip bounds ------------
__global__ void k2b_kernel() {
    __shared__ float red[256];
    const int tid = threadIdx.x;
    float a = 0.0f;
    for (int i = tid; i < ZCH * PBLK; i += 256) a += g_partial[i];
    red[tid] = a;
    __syncthreads();
    for (int s = 128; s > 0; s >>= 1) {
        if (tid < s) red[tid] += red[tid + s];
        __syncthreads();
    }
    if (tid == 0) {
        float mean = red[0] / (float)O3;
        g_clip[0] = mean * 0.001f;
        g_clip[1] = mean * 1000.0f;
    }
}

// ---------------- K3: recompute var from channels, exp, float4 ----------------
#define Q4 (O3 / 4)    // 549250

__global__ __launch_bounds__(256) void k3_kernel(float* __restrict__ out) {
    const int v4 = blockIdx.x * 256 + threadIdx.x;
    if (v4 >= Q4) return;
    float4* o4 = (float4*)out;

    float4 m[CH];
    #pragma unroll
    for (int c = 0; c < CH; c++) m[c] = o4[(size_t)c * Q4 + v4];

    float sx = 0.f, sy = 0.f, sz = 0.f, sw = 0.f;
    #pragma unroll
    for (int c = 0; c < CH; c++) {
        sx += m[c].x; sy += m[c].y; sz += m[c].z; sw += m[c].w;
    }
    const float lo = g_clip[0], hi = g_clip[1];
    float ix = 1.0f / fminf(fmaxf(sx * (1.0f/12.0f), lo), hi);
    float iy = 1.0f / fminf(fmaxf(sy * (1.0f/12.0f), lo), hi);
    float iz = 1.0f / fminf(fmaxf(sz * (1.0f/12.0f), lo), hi);
    float iw = 1.0f / fminf(fmaxf(sw * (1.0f/12.0f), lo), hi);

    #pragma unroll
    for (int c = 0; c < CH; c++) {
        float4 r;
        r.x = __expf(-m[c].x * ix);
        r.y = __expf(-m[c].y * iy);
        r.z = __expf(-m[c].z * iz);
        r.w = __expf(-m[c].w * iw);
        o4[(size_t)c * Q4 + v4] = r;
    }
}

// ---------------- launch ----------------
extern "C" void kernel_launch(void* const* d_in, const int* in_sizes, int n_in,
                              void* d_out, int out_size) {
    const float* x = (const float*)d_in[0];
    float* out = (float*)d_out;

    cudaFuncSetAttribute(k1_kernel,
                         cudaFuncAttributeMaxDynamicSharedMemorySize, K1_SMEM);

    dim3 g1(NSTRIP, O);
    k1_kernel<<<g1, 256, K1_SMEM>>>(x);

    dim3 g2(PBLK, ZCH);
    k2_kernel<<<g2, 256>>>(out);

    k2b_kernel<<<1, 256>>>();

    k3_kernel<<<(Q4 + 255) / 256, 256>>>(out);
}